// round 15
// baseline (speedup 1.0000x reference)
#include <cuda_runtime.h>
#include <cuda_bf16.h>

#define PADW 68

typedef unsigned long long u64;

__device__ __forceinline__ u64 ffma2(u64 a, u64 b, u64 c){
    u64 d; asm("fma.rn.f32x2 %0, %1, %2, %3;" : "=l"(d) : "l"(a), "l"(b), "l"(c)); return d;
}
__device__ __forceinline__ u64 fmul2(u64 a, u64 b){
    u64 d; asm("mul.rn.f32x2 %0, %1, %2;" : "=l"(d) : "l"(a), "l"(b)); return d;
}
__device__ __forceinline__ u64 dup2(float x){
    u64 d; asm("mov.b64 %0, {%1, %1};" : "=l"(d) : "f"(x)); return d;
}
__device__ __forceinline__ float hadd2(u64 a){
    float lo, hi; asm("mov.b64 {%0, %1}, %2;" : "=f"(lo), "=f"(hi) : "l"(a)); return lo + hi;
}
__device__ __forceinline__ u64 sub2(u64 a, u64 b){      // a - b
    return ffma2(b, dup2(-1.f), a);
}
__device__ __forceinline__ u64 div2(u64 a, u64 b){      // a / b (fast)
    float al, ah, bl, bh;
    asm("mov.b64 {%0,%1}, %2;" : "=f"(al), "=f"(ah) : "l"(a));
    asm("mov.b64 {%0,%1}, %2;" : "=f"(bl), "=f"(bh) : "l"(b));
    float cl = __fdividef(al, bl), ch = __fdividef(ah, bh);
    u64 d; asm("mov.b64 %0, {%1,%2};" : "=l"(d) : "f"(cl), "f"(ch)); return d;
}

__device__ float g_states[2*16*32*64*64];
__device__ float g_y[2*2048*16*64];

// ---------------------------------------------------------------------------
// SSD chunk body (unchanged, passing since R1).
// ---------------------------------------------------------------------------
__device__ void ssd_chunk_body(int blk, float* sm,
    const float* __restrict__ Xg, const float* __restrict__ Ag,
    const float* __restrict__ Bg, const float* __restrict__ Cg,
    float* __restrict__ out)
{
    float* sC   = sm;
    float* sB   = sC + 64*PADW;
    float* sX   = sB + 64*PADW;
    float* sG   = sX + 64*PADW;
    float* sCum = sG + 64*PADW;
    float* sDec = sCum + 64;

    int c  = blk & 31;
    int bh = blk >> 5;
    int b  = bh >> 4, h = bh & 15;
    int tid = threadIdx.x;

    long long gbase = ((long long)b*2048 + c*64)*1024 + h*64;

    for (int e = tid; e < 4096; e += 256){
        int l = e >> 6, p = e & 63;
        long long gi = gbase + (long long)l*1024 + p;
        int si = l*PADW + p;
        sC[si] = Cg[gi];
        sB[si] = Bg[gi];
        sX[si] = Xg[gi];
    }
    if (tid < 64) sCum[tid] = Ag[((long long)b*2048 + c*64 + tid)*16 + h];
    __syncthreads();
    if (tid == 0){
        float run = 0.f;
        for (int l = 0; l < 64; l++){ run += sCum[l]; sCum[l] = run; }
    }
    __syncthreads();
    if (tid < 64) sDec[tid] = expf(sCum[63] - sCum[tid]);

    int l  = tid >> 2;
    int pg = tid & 3;

    float g[16];
#pragma unroll
    for (int i = 0; i < 16; i++) g[i] = 0.f;
    {
        const float4* c4 = (const float4*)(sC + l*PADW);
#pragma unroll 4
        for (int n4 = 0; n4 < 16; n4++){
            float4 cv = c4[n4];
#pragma unroll
            for (int si = 0; si < 16; si++){
                int s = 4*si + pg;
                float4 bv = ((const float4*)(sB + s*PADW))[n4];
                g[si] += cv.x*bv.x + cv.y*bv.y + cv.z*bv.z + cv.w*bv.w;
            }
        }
    }
    float cuml = sCum[l];
#pragma unroll
    for (int si = 0; si < 16; si++){
        int s = 4*si + pg;
        sG[l*PADW + s] = (s <= l) ? g[si]*expf(cuml - sCum[s]) : 0.f;
    }
    __syncthreads();

    float acc[16];
#pragma unroll
    for (int i = 0; i < 16; i++) acc[i] = 0.f;
    for (int s = 0; s < 64; s++){
        float gv = sG[l*PADW + s];
        const float4* x4 = (const float4*)(sX + s*PADW) + pg*4;
#pragma unroll
        for (int q4 = 0; q4 < 4; q4++){
            float4 xv = x4[q4];
            acc[q4*4+0] += gv*xv.x;
            acc[q4*4+1] += gv*xv.y;
            acc[q4*4+2] += gv*xv.z;
            acc[q4*4+3] += gv*xv.w;
        }
    }
    {
        float4* op = (float4*)(out + gbase + (long long)l*1024 + pg*16);
#pragma unroll
        for (int q4 = 0; q4 < 4; q4++){
            float4 ov;
            ov.x = acc[q4*4+0]; ov.y = acc[q4*4+1];
            ov.z = acc[q4*4+2]; ov.w = acc[q4*4+3];
            op[q4] = ov;
        }
    }

    int pp = tid >> 2, ng = tid & 3;
#pragma unroll
    for (int i = 0; i < 16; i++) acc[i] = 0.f;
    for (int l2 = 0; l2 < 64; l2++){
        float t = sDec[l2] * sX[l2*PADW + pp];
        const float4* b4 = (const float4*)(sB + l2*PADW) + ng*4;
#pragma unroll
        for (int q4 = 0; q4 < 4; q4++){
            float4 bv = b4[q4];
            acc[q4*4+0] += t*bv.x;
            acc[q4*4+1] += t*bv.y;
            acc[q4*4+2] += t*bv.z;
            acc[q4*4+3] += t*bv.w;
        }
    }
    {
        float4* sp = (float4*)(g_states + ((long long)bh*32 + c)*4096 + pp*64 + ng*16);
#pragma unroll
        for (int q4 = 0; q4 < 4; q4++){
            float4 sv;
            sv.x = acc[q4*4+0]; sv.y = acc[q4*4+1];
            sv.z = acc[q4*4+2]; sv.w = acc[q4*4+3];
            sp[q4] = sv;
        }
    }
}

// ---------------------------------------------------------------------------
// WKV v5: chunked delta-rule, blocks of T=8 steps, 2 barriers per block.
// Warp g owns S rows 8g..8g+7; lane (rr=lane>>2, q=lane&3) = (row, 16 cols).
// Per block: phase1 M[t]=S.k_t (all warps) | bar | warp-0 triangular solve
// (8 rounds, batched parallel dots, no barriers) | bar | y + rank-8 S update.
// ---------------------------------------------------------------------------
#define WTILE 16
#define SLOT  320     // k(0) v(64) w(128) b(192) r(256)
#define OFF_M (2*WTILE*SLOT)
#define OFF_D (OFF_M + 512)
#define OFF_A (OFF_D + 512)

__device__ void wkv_body(float* sh,
    const float* __restrict__ rg, const float* __restrict__ kg,
    const float* __restrict__ vg, const float* __restrict__ wg,
    const float* __restrict__ bg)
{
    float* sM = sh + OFF_M;   // [8][64]  M[t][i] = (S k_t)[i]
    float* sD = sh + OFF_D;   // [8][64]  delta_s
    float* sA = sh + OFF_A;   // [8]      A[s][s]

    int bw = blockIdx.x;
    int bq = bw >> 4, h = bw & 15;
    int tid = threadIdx.x;
    int wid = tid >> 5, lane = tid & 31;
    int rr = lane >> 2, q = lane & 3;
    int row = wid*8 + rr;
    int c0 = q*16;
    int e2 = lane*2;

    long long base  = (long long)bw * 2048 * 64;
    long long obase = (long long)bq * 2048 * 1024 + h * 64;
    const float* kb = kg + base;
    const float* vb = vg + base;
    const float* wb = wg + base;
    const float* bb = bg + base;
    const float* rb = rg + base;
    float* gyb = g_y + obase;

    auto stage = [&](int n, float* dst){
#pragma unroll 1
        for (int c = tid; c < 5*256; c += 256){
            int a = c >> 8, rem = c & 255, t = rem >> 4, off = (rem & 15) << 2;
            long long so = (long long)(16*n + t)*64 + off;
            const float* src;
            if      (a == 0) src = kb + so;
            else if (a == 1) src = vb + so;
            else if (a == 2) src = wb + so;
            else if (a == 3) src = bb + so;
            else             src = rb + so;
            unsigned du = (unsigned)__cvta_generic_to_shared(dst + (t*5 + a)*64 + off);
            asm volatile("cp.async.cg.shared.global [%0], [%1], 16;" :: "r"(du), "l"(src));
        }
        asm volatile("cp.async.commit_group;" ::: "memory");
    };

    u64 S[8];
#pragma unroll
    for (int m = 0; m < 8; m++) S[m] = 0ull;

    stage(0, sh);

    for (int n = 0; n < 128; n++){
        float* buf = sh + (n & 1)*WTILE*SLOT;
        if (n < 127){
            stage(n + 1, sh + ((n + 1) & 1)*WTILE*SLOT);
            asm volatile("cp.async.wait_group 1;" ::: "memory");
        } else {
            asm volatile("cp.async.wait_group 0;" ::: "memory");
        }
        __syncthreads();

        for (int half = 0; half < 2; half++){
            const float* tp = buf + half*8*SLOT;
            long long t0 = (long long)(n*16 + half*8);

            // ---- phase 1: M[t][row] (own row, 4-lane reduce) ----
            float mp[8];
#pragma unroll
            for (int t = 0; t < 8; t++){
                const ulonglong2* kp = (const ulonglong2*)(tp + t*SLOT + c0);
                ulonglong2 ka = kp[0], kb4 = kp[1], kc = kp[2], kd = kp[3];
                u64 acc = fmul2(S[0], ka.x);
                acc = ffma2(S[1], ka.y,  acc);
                acc = ffma2(S[2], kb4.x, acc);
                acc = ffma2(S[3], kb4.y, acc);
                acc = ffma2(S[4], kc.x,  acc);
                acc = ffma2(S[5], kc.y,  acc);
                acc = ffma2(S[6], kd.x,  acc);
                acc = ffma2(S[7], kd.y,  acc);
                float p = hadd2(acc);
                p += __shfl_xor_sync(0xffffffffu, p, 1);
                p += __shfl_xor_sync(0xffffffffu, p, 2);
                mp[t] = p;
            }
            if (q == 0){
#pragma unroll
                for (int t = 0; t < 8; t++) sM[t*64 + row] = mp[t];
            }
            __syncthreads();

            // ---- solve: warp 0 only, elements (2l, 2l+1) per lane ----
            if (wid == 0){
                u64 kk[8];
#pragma unroll
                for (int s = 0; s < 8; s++) kk[s] = *(const u64*)(tp + s*SLOT + e2);
                u64 ACC[8];
#pragma unroll
                for (int s = 0; s < 8; s++) ACC[s] = 0ull;
                u64 Wex = dup2(1.f);
#pragma unroll
                for (int s = 0; s < 8; s++){
                    u64 ws = *(const u64*)(tp + s*SLOT + 128 + e2);
                    u64 bs = *(const u64*)(tp + s*SLOT + 192 + e2);
                    u64 vs = *(const u64*)(tp + s*SLOT +  64 + e2);
                    u64 Ms = *(const u64*)(sM + s*64 + e2);
                    u64 Win = fmul2(Wex, ws);
                    u64 us  = fmul2(bs, kk[s]);
                    u64 gh  = div2(us, Win);
                    u64 vh  = sub2(div2(vs, Wex), Ms);
                    u64 dh  = sub2(vh, ACC[s]);          // delta_hat_s
                    u64 eps = fmul2(Wex, dh);            // delta_s
                    *(u64*)(sD + s*64 + e2) = eps;
                    float a[8];
#pragma unroll
                    for (int t = 0; t < 8; t++) if (t >= s) a[t] = hadd2(fmul2(eps, kk[t]));
#pragma unroll
                    for (int lv = 1; lv <= 16; lv <<= 1){
#pragma unroll
                        for (int t = 0; t < 8; t++) if (t >= s)
                            a[t] += __shfl_xor_sync(0xffffffffu, a[t], lv);
                    }
                    if (lane == 0) sA[s] = a[s];
#pragma unroll
                    for (int t = 0; t < 8; t++) if (t > s)
                        ACC[t] = ffma2(dup2(a[t]), gh, ACC[t]);
                    Wex = Win;
                }
            }
            __syncthreads();

            // ---- y + rank-8 S update (own row); no bar before next phase1 ----
            float Wr = 1.f;
            float* gyr = gyb + t0*1024 + row;
#pragma unroll
            for (int t = 0; t < 8; t++){
                float wt = tp[t*SLOT + 128 + row];
                float kt = tp[t*SLOT +   0 + row];
                float bt = tp[t*SLOT + 192 + row];
                float ut = bt * kt;
                float Win = Wr * wt;
                float ghr = __fdividef(ut, Win);
                const ulonglong2* dp = (const ulonglong2*)(sD + t*64 + c0);
                ulonglong2 da = dp[0], db4 = dp[1], dc = dp[2], dd = dp[3];
                u64 g2 = dup2(ghr);
                S[0] = ffma2(g2, da.x,  S[0]);
                S[1] = ffma2(g2, da.y,  S[1]);
                S[2] = ffma2(g2, db4.x, S[2]);
                S[3] = ffma2(g2, db4.y, S[3]);
                S[4] = ffma2(g2, dc.x,  S[4]);
                S[5] = ffma2(g2, dc.y,  S[5]);
                S[6] = ffma2(g2, dd.x,  S[6]);
                S[7] = ffma2(g2, dd.y,  S[7]);
                if (q == 0){
                    float vt = tp[t*SLOT +  64 + row];
                    float rt = tp[t*SLOT + 256 + row];
                    float dt = sD[t*64 + row];
                    gyr[0] = rt * (wt*(vt - dt) + ut*sA[t]);
                }
                gyr += 1024;
                Wr = Win;
            }
            u64 w2 = dup2(Wr);
#pragma unroll
            for (int m = 0; m < 8; m++) S[m] = fmul2(w2, S[m]);
        }
    }
}

// ---------------------------------------------------------------------------
__global__ __launch_bounds__(256) void fused_kernel(
    const float* __restrict__ Xg, const float* __restrict__ Ag,
    const float* __restrict__ Bg, const float* __restrict__ Cg,
    const float* __restrict__ rg, const float* __restrict__ kg,
    const float* __restrict__ vg, const float* __restrict__ wg,
    const float* __restrict__ bg, float* __restrict__ out)
{
    extern __shared__ float sm[];
    if (blockIdx.x < 32) wkv_body(sm, rg, kg, vg, wg, bg);
    else                 ssd_chunk_body(blockIdx.x - 32, sm, Xg, Ag, Bg, Cg, out);
}

// ---------------------------------------------------------------------------
__global__ __launch_bounds__(256) void ssd_state_scan_kernel(const float* __restrict__ Ag)
{
    int bh = blockIdx.x;
    int b = bh >> 4, h = bh & 15;
    __shared__ float atot[32];
    int tid = threadIdx.x;
    if (tid < 32){
        float s = 0.f;
        long long base = ((long long)b*2048 + tid*64)*16 + h;
        for (int l = 0; l < 64; l++) s += Ag[base + (long long)l*16];
        atot[tid] = s;
    }
    __syncthreads();
    float S[16];
#pragma unroll
    for (int i = 0; i < 16; i++) S[i] = 0.f;
    float* base = g_states + (long long)bh*32*4096;
    for (int c = 0; c < 32; c++){
        float dec = expf(atot[c]);
        float* p = base + (long long)c*4096;
#pragma unroll
        for (int r2 = 0; r2 < 16; r2++){
            int e = r2*256 + tid;
            float st = p[e];
            p[e] = S[r2];
            S[r2] = S[r2]*dec + st;
        }
    }
}

// ---------------------------------------------------------------------------
__global__ __launch_bounds__(256) void ssd_yoff_kernel(
    const float* __restrict__ Ag, const float* __restrict__ Cg,
    float* __restrict__ out)
{
    __shared__ float sC[64*PADW];
    __shared__ float sS[64*PADW];
    __shared__ float sCum[64];
    int blk = blockIdx.x;
    int c  = blk & 31;
    int bh = blk >> 5;
    int b  = bh >> 4, h = bh & 15;
    int tid = threadIdx.x;
    long long gbase = ((long long)b*2048 + c*64)*1024 + h*64;
    const float* st = g_states + ((long long)bh*32 + c)*4096;

    for (int e = tid; e < 4096; e += 256){
        int l = e >> 6, p = e & 63;
        sC[l*PADW + p] = Cg[gbase + (long long)l*1024 + p];
        sS[p*PADW + l] = st[(l << 6) | p];
    }
    if (tid < 64) sCum[tid] = Ag[((long long)b*2048 + c*64 + tid)*16 + h];
    __syncthreads();
    if (tid == 0){
        float run = 0.f;
        for (int l = 0; l < 64; l++){ run += sCum[l]; sCum[l] = run; }
    }
    __syncthreads();

    int l  = tid >> 2;
    int pg = tid & 3;
    float acc[16];
#pragma unroll
    for (int i = 0; i < 16; i++) acc[i] = 0.f;
    for (int n = 0; n < 64; n++){
        float cv = sC[l*PADW + n];
        const float4* s4 = (const float4*)(sS + n*PADW) + pg*4;
#pragma unroll
        for (int q4 = 0; q4 < 4; q4++){
            float4 sv = s4[q4];
            acc[q4*4+0] += cv*sv.x;
            acc[q4*4+1] += cv*sv.y;
            acc[q4*4+2] += cv*sv.z;
            acc[q4*4+3] += cv*sv.w;
        }
    }
    float d = expf(sCum[l]);
    float4* op = (float4*)(out + gbase + (long long)l*1024 + pg*16);
    const float4* gp = (const float4*)(g_y + gbase + (long long)l*1024 + pg*16);
#pragma unroll
    for (int q4 = 0; q4 < 4; q4++){
        float4 ov = op[q4];
        float4 gv = gp[q4];
        ov.x += d*acc[q4*4+0] + gv.x;
        ov.y += d*acc[q4*4+1] + gv.y;
        ov.z += d*acc[q4*4+2] + gv.z;
        ov.w += d*acc[q4*4+3] + gv.w;
        op[q4] = ov;
    }
}

// ---------------------------------------------------------------------------
extern "C" void kernel_launch(void* const* d_in, const int* in_sizes, int n_in,
                              void* d_out, int out_size)
{
    const float* X  = (const float*)d_in[0];
    const float* A  = (const float*)d_in[1];
    const float* B  = (const float*)d_in[2];
    const float* C  = (const float*)d_in[3];
    const float* r  = (const float*)d_in[4];
    const float* k  = (const float*)d_in[5];
    const float* v  = (const float*)d_in[6];
    const float* w  = (const float*)d_in[7];
    const float* bn = (const float*)d_in[8];
    float* out = (float*)d_out;

    const size_t smemF = 120 * 1024;   // 1 block/SM: wkv SMs stay isolated
    cudaFuncSetAttribute(fused_kernel,
                         cudaFuncAttributeMaxDynamicSharedMemorySize, (int)smemF);

    fused_kernel<<<32 + 1024, 256, smemF>>>(X, A, B, C, r, k, v, w, bn, out);
    ssd_state_scan_kernel<<<32, 256>>>(A);
    ssd_yoff_kernel<<<1024, 256>>>(A, C, out);
}

// round 16
// speedup vs baseline: 1.7613x; 1.7613x over previous
#include <cuda_runtime.h>
#include <cuda_bf16.h>

#define PADW 68

typedef unsigned long long u64;

// ---- packed f32x2 helpers (sm_103a FFMA2) ----
__device__ __forceinline__ u64 ffma2(u64 a, u64 b, u64 c){
    u64 d; asm("fma.rn.f32x2 %0, %1, %2, %3;" : "=l"(d) : "l"(a), "l"(b), "l"(c)); return d;
}
__device__ __forceinline__ u64 fmul2(u64 a, u64 b){
    u64 d; asm("mul.rn.f32x2 %0, %1, %2;" : "=l"(d) : "l"(a), "l"(b)); return d;
}
__device__ __forceinline__ u64 dup2(float x){
    u64 d; asm("mov.b64 %0, {%1, %1};" : "=l"(d) : "f"(x)); return d;
}
__device__ __forceinline__ float hadd2(u64 a){
    float lo, hi; asm("mov.b64 {%0, %1}, %2;" : "=f"(lo), "=f"(hi) : "l"(a)); return lo + hi;
}

// ---- cross-block sync primitives ----
__device__ __forceinline__ int ld_acq(const int* p){
    int v; asm volatile("ld.acquire.gpu.b32 %0, [%1];" : "=r"(v) : "l"(p) : "memory"); return v;
}

// scratch + flags
__device__ float g_states[2*16*32*64*64];
__device__ float g_y[2*2048*16*64];
__device__ int   g_c1 = 0;        // #ssd chunk blocks done (1024)
__device__ int   g_c2 = 0;        // #scan/yoff blocks done (32)
__device__ int   g_prog[32] = {}; // wkv 64-step-chunk progress per (b,h)

// ---------------------------------------------------------------------------
// SSD chunk body (unchanged, passing since R1). 256 threads.
// ---------------------------------------------------------------------------
__device__ void ssd_chunk_body(int blk, float* sm,
    const float* __restrict__ Xg, const float* __restrict__ Ag,
    const float* __restrict__ Bg, const float* __restrict__ Cg,
    float* __restrict__ out)
{
    float* sC   = sm;
    float* sB   = sC + 64*PADW;
    float* sX   = sB + 64*PADW;
    float* sG   = sX + 64*PADW;
    float* sCum = sG + 64*PADW;
    float* sDec = sCum + 64;

    int c  = blk & 31;
    int bh = blk >> 5;
    int b  = bh >> 4, h = bh & 15;
    int tid = threadIdx.x;

    long long gbase = ((long long)b*2048 + c*64)*1024 + h*64;

    for (int e = tid; e < 4096; e += 256){
        int l = e >> 6, p = e & 63;
        long long gi = gbase + (long long)l*1024 + p;
        int si = l*PADW + p;
        sC[si] = Cg[gi];
        sB[si] = Bg[gi];
        sX[si] = Xg[gi];
    }
    if (tid < 64) sCum[tid] = Ag[((long long)b*2048 + c*64 + tid)*16 + h];
    __syncthreads();
    if (tid == 0){
        float run = 0.f;
        for (int l = 0; l < 64; l++){ run += sCum[l]; sCum[l] = run; }
    }
    __syncthreads();
    if (tid < 64) sDec[tid] = expf(sCum[63] - sCum[tid]);

    int l  = tid >> 2;
    int pg = tid & 3;

    float g[16];
#pragma unroll
    for (int i = 0; i < 16; i++) g[i] = 0.f;
    {
        const float4* c4 = (const float4*)(sC + l*PADW);
#pragma unroll 4
        for (int n4 = 0; n4 < 16; n4++){
            float4 cv = c4[n4];
#pragma unroll
            for (int si = 0; si < 16; si++){
                int s = 4*si + pg;
                float4 bv = ((const float4*)(sB + s*PADW))[n4];
                g[si] += cv.x*bv.x + cv.y*bv.y + cv.z*bv.z + cv.w*bv.w;
            }
        }
    }
    float cuml = sCum[l];
#pragma unroll
    for (int si = 0; si < 16; si++){
        int s = 4*si + pg;
        sG[l*PADW + s] = (s <= l) ? g[si]*expf(cuml - sCum[s]) : 0.f;
    }
    __syncthreads();

    float acc[16];
#pragma unroll
    for (int i = 0; i < 16; i++) acc[i] = 0.f;
    for (int s = 0; s < 64; s++){
        float gv = sG[l*PADW + s];
        const float4* x4 = (const float4*)(sX + s*PADW) + pg*4;
#pragma unroll
        for (int q4 = 0; q4 < 4; q4++){
            float4 xv = x4[q4];
            acc[q4*4+0] += gv*xv.x;
            acc[q4*4+1] += gv*xv.y;
            acc[q4*4+2] += gv*xv.z;
            acc[q4*4+3] += gv*xv.w;
        }
    }
    {
        float4* op = (float4*)(out + gbase + (long long)l*1024 + pg*16);
#pragma unroll
        for (int q4 = 0; q4 < 4; q4++){
            float4 ov;
            ov.x = acc[q4*4+0]; ov.y = acc[q4*4+1];
            ov.z = acc[q4*4+2]; ov.w = acc[q4*4+3];
            op[q4] = ov;
        }
    }

    int pp = tid >> 2, ng = tid & 3;
#pragma unroll
    for (int i = 0; i < 16; i++) acc[i] = 0.f;
    for (int l2 = 0; l2 < 64; l2++){
        float t = sDec[l2] * sX[l2*PADW + pp];
        const float4* b4 = (const float4*)(sB + l2*PADW) + ng*4;
#pragma unroll
        for (int q4 = 0; q4 < 4; q4++){
            float4 bv = b4[q4];
            acc[q4*4+0] += t*bv.x;
            acc[q4*4+1] += t*bv.y;
            acc[q4*4+2] += t*bv.z;
            acc[q4*4+3] += t*bv.w;
        }
    }
    {
        float4* sp = (float4*)(g_states + ((long long)bh*32 + c)*4096 + pp*64 + ng*16);
#pragma unroll
        for (int q4 = 0; q4 < 4; q4++){
            float4 sv;
            sv.x = acc[q4*4+0]; sv.y = acc[q4*4+1];
            sv.z = acc[q4*4+2]; sv.w = acc[q4*4+3];
            sp[q4] = sv;
        }
    }
}

// ---------------------------------------------------------------------------
// WKV body — v2 step (best: 600cyc/step), + per-64-step progress release.
// ---------------------------------------------------------------------------
#define WTILE 32
#define SLOT  320    // k(64) v(64) w(64) b(64) r(64)

__device__ void wkv_body(float* sh,
    const float* __restrict__ rg, const float* __restrict__ kg,
    const float* __restrict__ vg, const float* __restrict__ wg,
    const float* __restrict__ bg)
{
    float* dsp = sh + 2*WTILE*SLOT;   // [2][64] delta double buffer

    int bw = blockIdx.x;
    int bq = bw >> 4, h = bw & 15;
    int tid = threadIdx.x, i = tid >> 2, q = tid & 3, j0 = q * 16;
    long long base  = (long long)bw * 2048 * 64;
    long long obase = (long long)bq * 2048 * 1024 + h * 64;

    const float* kb = kg + base;
    const float* vb = vg + base;
    const float* wb = wg + base;
    const float* bb = bg + base;
    const float* rb = rg + base;
    float* gyb = g_y + obase;

    auto stage = [&](int n, float* dst){
#pragma unroll 1
        for (int c = tid; c < 5*512; c += 256){
            int a = c >> 9, rem = c & 511, t = rem >> 4, off = (rem & 15) << 2;
            int s = 32*n + 1 + t; if (s > 2047) s = 2047;
            const float* src;
            long long so = (long long)s*64 + off;
            if      (a == 0) src = kb + so;
            else if (a == 1) src = vb + so;
            else if (a == 2) src = wb + so;
            else if (a == 3) src = bb + so;
            else             src = rb + so;
            unsigned du = (unsigned)__cvta_generic_to_shared(dst + (t*5 + a)*64 + off);
            asm volatile("cp.async.cg.shared.global [%0], [%1], 16;" :: "r"(du), "l"(src));
        }
        asm volatile("cp.async.commit_group;" ::: "memory");
    };

    u64 S[8];
#pragma unroll
    for (int m = 0; m < 8; m++) S[m] = 0ull;

    stage(0, sh);

    u64 kj[8];
    {
        const ulonglong2* kp = (const ulonglong2*)(kb + j0);
#pragma unroll
        for (int m = 0; m < 4; m++){ ulonglong2 t2 = kp[m]; kj[2*m] = t2.x; kj[2*m+1] = t2.y; }
    }
    float wi  = wb[i];
    float bki = bb[i] * kb[i];
    float ri  = rb[i];
    if (q == 0) dsp[i] = vb[i];
    float sk = 0.f;

    for (int n = 0; n < 64; n++){
        float* buf = sh + (n & 1)*WTILE*SLOT;
        if (n < 63){
            stage(n + 1, sh + ((n + 1) & 1)*WTILE*SLOT);
            asm volatile("cp.async.wait_group 1;" ::: "memory");
        } else {
            asm volatile("cp.async.wait_group 0;" ::: "memory");
        }
        __syncthreads();

        float* gyr = gyb + (long long)(n*32)*1024;
#pragma unroll 4
        for (int tt = 0; tt < WTILE; tt++){
            int p = tt & 1;

            // A: consume delta_t
            u64 d2[8];
            {
                const ulonglong2* dp = (const ulonglong2*)(dsp + p*64 + j0);
#pragma unroll
                for (int m = 0; m < 4; m++){ ulonglong2 t2 = dp[m]; d2[2*m] = t2.x; d2[2*m+1] = t2.y; }
            }
            u64 a0 = 0ull, a1 = 0ull;
#pragma unroll
            for (int m = 0; m < 8; m += 2){
                a0 = ffma2(d2[m],   kj[m],   a0);
                a1 = ffma2(d2[m+1], kj[m+1], a1);
            }
            float dkk = hadd2(a0) + hadd2(a1);
            dkk += __shfl_xor_sync(0xffffffffu, dkk, 1);
            dkk += __shfl_xor_sync(0xffffffffu, dkk, 2);

            if (q == 0){
                gyr[i] = ri * (wi*sk + bki*dkk);
            }

            u64 w2 = dup2(wi), bk2 = dup2(bki);
#pragma unroll
            for (int m = 0; m < 8; m++)
                S[m] = ffma2(S[m], w2, fmul2(bk2, d2[m]));

            // B: produce delta_{t+1}
            const float* stp = buf + tt*SLOT;
            {
                const ulonglong2* kp = (const ulonglong2*)(stp + j0);
#pragma unroll
                for (int m = 0; m < 4; m++){ ulonglong2 t2 = kp[m]; kj[2*m] = t2.x; kj[2*m+1] = t2.y; }
            }
            u64 b0 = 0ull, b1 = 0ull;
#pragma unroll
            for (int m = 0; m < 8; m += 2){
                b0 = ffma2(S[m],   kj[m],   b0);
                b1 = ffma2(S[m+1], kj[m+1], b1);
            }
            float skn = hadd2(b0) + hadd2(b1);
            skn += __shfl_xor_sync(0xffffffffu, skn, 1);
            skn += __shfl_xor_sync(0xffffffffu, skn, 2);

            wi  = stp[128 + i];
            bki = stp[192 + i] * stp[i];
            if (q == 0){
                ri = stp[256 + i];
                float vi = stp[64 + i];
                dsp[(p ^ 1)*64 + i] = vi - skn;
            }
            sk = skn;
            gyr += 1024;
            __syncthreads();
        }

        // publish progress every 64 steps (2 tiles): chunk (n>>1) complete
        if (n & 1){
            __threadfence();
            __syncthreads();
            if (tid == 0) atomicAdd(&g_prog[bw], 1);
        }
    }
}

// ---------------------------------------------------------------------------
// Cross-chunk state scan for one (b,h). 256 threads. g_states in place.
// ---------------------------------------------------------------------------
__device__ void scan_body(int bh, float* sm, const float* __restrict__ Ag)
{
    int b = bh >> 4, h = bh & 15;
    float* atot = sm;                 // 32 floats
    int tid = threadIdx.x;
    if (tid < 32){
        float s = 0.f;
        long long base = ((long long)b*2048 + tid*64)*16 + h;
        for (int l = 0; l < 64; l++) s += Ag[base + (long long)l*16];
        atot[tid] = s;
    }
    __syncthreads();
    float S[16];
#pragma unroll
    for (int i = 0; i < 16; i++) S[i] = 0.f;
    float* base = g_states + (long long)bh*32*4096;
    for (int c = 0; c < 32; c++){
        float dec = expf(atot[c]);
        float* p = base + (long long)c*4096;
#pragma unroll
        for (int r2 = 0; r2 < 16; r2++){
            int e = r2*256 + tid;
            float st = p[e];
            p[e] = S[r2];
            S[r2] = S[r2]*dec + st;
        }
    }
    __syncthreads();
}

// ---------------------------------------------------------------------------
// Y_off + g_y add for one (b,h,c). 256 threads, smem from dynamic buffer.
// out = Y_diag (already there) + Y_off + g_y
// ---------------------------------------------------------------------------
__device__ void yoff_chunk(int bh, int c, float* sm,
    const float* __restrict__ Ag, const float* __restrict__ Cg,
    float* __restrict__ out)
{
    float* sC   = sm;
    float* sS   = sC + 64*PADW;
    float* sCum = sS + 64*PADW;
    int b  = bh >> 4, h = bh & 15;
    int tid = threadIdx.x;
    long long gbase = ((long long)b*2048 + c*64)*1024 + h*64;
    const float* st = g_states + ((long long)bh*32 + c)*4096;

    for (int e = tid; e < 4096; e += 256){
        int l = e >> 6, p = e & 63;        // l == pp, p == n
        sC[l*PADW + p] = Cg[gbase + (long long)l*1024 + p];
        sS[p*PADW + l] = st[(l << 6) | p]; // transposed [n][pp]
    }
    if (tid < 64) sCum[tid] = Ag[((long long)b*2048 + c*64 + tid)*16 + h];
    __syncthreads();
    if (tid == 0){
        float run = 0.f;
        for (int l = 0; l < 64; l++){ run += sCum[l]; sCum[l] = run; }
    }
    __syncthreads();

    int l  = tid >> 2;
    int pg = tid & 3;
    float acc[16];
#pragma unroll
    for (int i = 0; i < 16; i++) acc[i] = 0.f;
    for (int n = 0; n < 64; n++){
        float cv = sC[l*PADW + n];
        const float4* s4 = (const float4*)(sS + n*PADW) + pg*4;
#pragma unroll
        for (int q4 = 0; q4 < 4; q4++){
            float4 sv = s4[q4];
            acc[q4*4+0] += cv*sv.x;
            acc[q4*4+1] += cv*sv.y;
            acc[q4*4+2] += cv*sv.z;
            acc[q4*4+3] += cv*sv.w;
        }
    }
    float d = expf(sCum[l]);
    float4* op = (float4*)(out + gbase + (long long)l*1024 + pg*16);
    const float4* gp = (const float4*)(g_y + gbase + (long long)l*1024 + pg*16);
#pragma unroll
    for (int q4 = 0; q4 < 4; q4++){
        float4 ov = op[q4];
        float4 gv = gp[q4];
        ov.x += d*acc[q4*4+0] + gv.x;
        ov.y += d*acc[q4*4+1] + gv.y;
        ov.z += d*acc[q4*4+2] + gv.z;
        ov.w += d*acc[q4*4+3] + gv.w;
        op[q4] = ov;
    }
    __syncthreads();   // smem reused next chunk
}

// ---------------------------------------------------------------------------
// Single fused launch, grid = 1088:
//   bid 0..31     : wkv (isolated 1 block/SM via 120KB smem) + progress flags
//   bid 32..1055  : ssd chunks -> release c1
//   bid 1056..1087: acquire c1 -> scan(bh) -> yoff chunks trailing wkv progress
// ---------------------------------------------------------------------------
__global__ __launch_bounds__(256) void fused_kernel(
    const float* __restrict__ Xg, const float* __restrict__ Ag,
    const float* __restrict__ Bg, const float* __restrict__ Cg,
    const float* __restrict__ rg, const float* __restrict__ kg,
    const float* __restrict__ vg, const float* __restrict__ wg,
    const float* __restrict__ bg, float* __restrict__ out)
{
    extern __shared__ float sm[];
    int tid = threadIdx.x;

    if (blockIdx.x < 32){
        wkv_body(sm, rg, kg, vg, wg, bg);
    }
    else if (blockIdx.x < 1056){
        ssd_chunk_body(blockIdx.x - 32, sm, Xg, Ag, Bg, Cg, out);
        __threadfence();
        __syncthreads();
        if (tid == 0) atomicAdd(&g_c1, 1);
    }
    else {
        int bh = blockIdx.x - 1056;
        // wait for all ssd chunk states + Y_diag
        if (tid == 0){
            while (ld_acq(&g_c1) < 1024) __nanosleep(128);
        }
        __syncthreads();
        scan_body(bh, sm, Ag);
        // yoff, trailing wkv's per-chunk progress
        for (int c = 0; c < 32; c++){
            if (tid == 0){
                while (ld_acq(&g_prog[bh]) <= c) __nanosleep(128);
            }
            __syncthreads();
            yoff_chunk(bh, c, sm, Ag, Cg, out);
        }
        // cleanup for next graph replay
        __threadfence();
        __syncthreads();
        if (tid == 0){
            g_prog[bh] = 0;
            int done = atomicAdd(&g_c2, 1);
            if (done == 31){ g_c1 = 0; g_c2 = 0; }
        }
    }
}

// ---------------------------------------------------------------------------
extern "C" void kernel_launch(void* const* d_in, const int* in_sizes, int n_in,
                              void* d_out, int out_size)
{
    const float* X  = (const float*)d_in[0];
    const float* A  = (const float*)d_in[1];
    const float* B  = (const float*)d_in[2];
    const float* C  = (const float*)d_in[3];
    const float* r  = (const float*)d_in[4];
    const float* k  = (const float*)d_in[5];
    const float* v  = (const float*)d_in[6];
    const float* w  = (const float*)d_in[7];
    const float* bn = (const float*)d_in[8];
    float* out = (float*)d_out;

    const size_t smemF = 120 * 1024;   // 1 block/SM: wkv SMs stay isolated
    cudaFuncSetAttribute(fused_kernel,
                         cudaFuncAttributeMaxDynamicSharedMemorySize, (int)smemF);

    fused_kernel<<<1088, 256, smemF>>>(X, A, B, C, r, k, v, w, bn, out);
}